// round 6
// baseline (speedup 1.0000x reference)
#include <cuda_runtime.h>
#include <cuda_bf16.h>
#include <cstdint>
#include <math.h>

#define BB 2
#define SS 2048
#define HH 1024
#define NHEADS 16
#define HDIM 64
#define MTOT (BB*SS)      // 4096
#define NQKV (3*HH)       // 3072

// Scratch (allocation-free rule: __device__ globals)
__device__ __nv_bfloat16 g_hid_bf[(size_t)MTOT * HH];    // 8 MiB
__device__ __nv_bfloat16 g_wq_bf[(size_t)HH * NQKV];     // 6 MiB
__device__ __nv_bfloat16 g_wd_bf[(size_t)HH * HH];       // 2 MiB
__device__ __nv_bfloat16 g_qkv_bf[(size_t)MTOT * NQKV];  // 24 MiB (Q pre-scaled 1/8)
__device__ __nv_bfloat16 g_ctx_bf[(size_t)MTOT * HH];    // 8 MiB
__device__ float g_x[(size_t)MTOT * HH];                 // 16 MiB

// ============================================================================
// helpers
// ============================================================================
__device__ __forceinline__ uint32_t smem_u32(const void* p) {
    uint32_t a;
    asm("{ .reg .u64 t; cvta.to.shared.u64 t, %1; cvt.u32.u64 %0, t; }"
        : "=r"(a) : "l"(p));
    return a;
}
__device__ __forceinline__ void cpasync16(uint32_t s, const void* g) {
    asm volatile("cp.async.cg.shared.global [%0], [%1], 16;" :: "r"(s), "l"(g));
}
#define CP_COMMIT() asm volatile("cp.async.commit_group;" ::: "memory")
#define CP_WAIT0()  asm volatile("cp.async.wait_group 0;" ::: "memory")
#define CP_WAIT1()  asm volatile("cp.async.wait_group 1;" ::: "memory")
#define CP_WAIT2()  asm volatile("cp.async.wait_group 2;" ::: "memory")

// pack two f32 -> bf16x2 (lo = first arg, hi = second arg)
__device__ __forceinline__ uint32_t pack_bf16(float lo, float hi) {
    uint32_t r;
    asm("cvt.rn.bf16x2.f32 %0, %1, %2;" : "=r"(r) : "f"(hi), "f"(lo));
    return r;
}

// m16n8k16 bf16 MMA, fp32 accumulate
__device__ __forceinline__ void mma_bf16(float c[4], const uint32_t a[4],
                                         const uint32_t b[2]) {
    asm volatile(
        "mma.sync.aligned.m16n8k16.row.col.f32.bf16.bf16.f32 "
        "{%0,%1,%2,%3}, {%4,%5,%6,%7}, {%8,%9}, {%0,%1,%2,%3};\n"
        : "+f"(c[0]), "+f"(c[1]), "+f"(c[2]), "+f"(c[3])
        : "r"(a[0]), "r"(a[1]), "r"(a[2]), "r"(a[3]), "r"(b[0]), "r"(b[1]));
}
__device__ __forceinline__ void ldmatrix_x4(uint32_t r[4], uint32_t addr) {
    asm volatile("ldmatrix.sync.aligned.m8n8.x4.shared.b16 {%0,%1,%2,%3}, [%4];"
                 : "=r"(r[0]), "=r"(r[1]), "=r"(r[2]), "=r"(r[3]) : "r"(addr));
}
__device__ __forceinline__ void ldmatrix_x4t(uint32_t r[4], uint32_t addr) {
    asm volatile("ldmatrix.sync.aligned.m8n8.x4.trans.shared.b16 {%0,%1,%2,%3}, [%4];"
                 : "=r"(r[0]), "=r"(r[1]), "=r"(r[2]), "=r"(r[3]) : "r"(addr));
}

// ============================================================================
// prep: fp32 -> bf16 convert
// ============================================================================
__global__ __launch_bounds__(256)
void f2bf_kernel(const float* __restrict__ in, __nv_bfloat16* __restrict__ out) {
    size_t i = (size_t)blockIdx.x * 256 + threadIdx.x;
    float4 v = ((const float4*)in)[i];
    uint2 o;
    o.x = pack_bf16(v.x, v.y);
    o.y = pack_bf16(v.z, v.w);
    ((uint2*)out)[i] = o;
}

// ============================================================================
// bf16 MMA GEMM: 128x128 CTA tile, BK=64, 256 threads (8 warps, 32x64 warp
// tiles). 4-stage cp.async ring (next stage issued RIGHT AFTER the barrier,
// overlapping full tile compute) + register fragment double-buffering so
// ldmatrix latency hides under the previous kc's 16 MMAs.
// ============================================================================
#define AS_STR 72
#define BS_STR 136
#define AS_ELE (128 * AS_STR)
#define BS_ELE (64 * BS_STR)
#define STAGE_ELE (AS_ELE + BS_ELE)
#define GEMM_STAGES 4
#define GEMM_SMEM_BYTES (GEMM_STAGES * STAGE_ELE * 2)   // 143360

template<bool QKV>
__global__ __launch_bounds__(256)
void gemm_bf16_kernel(const __nv_bfloat16* __restrict__ A,
                      const __nv_bfloat16* __restrict__ B,
                      const float* __restrict__ bias, const float* __restrict__ res,
                      void* __restrict__ Cout, int K, int N)
{
    extern __shared__ __align__(16) __nv_bfloat16 sh[];

    const int tid = threadIdx.x;
    const int w = tid >> 5, lane = tid & 31;
    const int g = lane >> 2, tig = lane & 3;
    const int wm = w >> 1, wn = w & 1;
    const int bm = blockIdx.y * 128, bn = blockIdx.x * 128;
    const int nst = K / 64;

    float cf[2][8][4];
#pragma unroll
    for (int mi = 0; mi < 2; mi++)
#pragma unroll
        for (int ni = 0; ni < 8; ni++)
#pragma unroll
            for (int q = 0; q < 4; q++) cf[mi][ni][q] = 0.0f;

    auto load_stage = [&](int st, int ks) {
        __nv_bfloat16* As = sh + st * STAGE_ELE;
        __nv_bfloat16* Bs = As + AS_ELE;
#pragma unroll
        for (int i = 0; i < 4; i++) {
            int l = tid + i * 256;
            int row = l >> 3, seg = l & 7;
            cpasync16(smem_u32(As + row * AS_STR + seg * 8),
                      A + (size_t)(bm + row) * K + ks * 64 + seg * 8);
        }
#pragma unroll
        for (int i = 0; i < 4; i++) {
            int l = tid + i * 256;
            int row = l >> 4, seg = l & 15;
            cpasync16(smem_u32(Bs + row * BS_STR + seg * 8),
                      B + (size_t)(ks * 64 + row) * N + bn + seg * 8);
        }
    };

    load_stage(0, 0); CP_COMMIT();
    load_stage(1, 1); CP_COMMIT();
    load_stage(2, 2); CP_COMMIT();

    const int l16 = lane & 15;
    const int lhi = (lane >> 4) * 8;

    uint32_t au[2][2][4];   // [slot][mi][4]
    uint32_t bu[2][8][2];   // [slot][ni][2]

    for (int ks = 0; ks < nst; ks++) {
        if (ks <= nst - 3)      { CP_WAIT2(); }
        else if (ks == nst - 2) { CP_WAIT1(); }
        else                    { CP_WAIT0(); }
        __syncthreads();

        // issue next stage immediately — slot (ks+3)%4 != ks%4, safe
        if (ks + 3 < nst) { load_stage((ks + 3) & 3, ks + 3); CP_COMMIT(); }

        const __nv_bfloat16* Ab = sh + (ks & 3) * STAGE_ELE;
        const __nv_bfloat16* Bb = Ab + AS_ELE;

        auto ldfrags = [&](int kc, int slot) {
#pragma unroll
            for (int mi = 0; mi < 2; mi++)
                ldmatrix_x4(au[slot][mi],
                            smem_u32(Ab + (wm * 32 + mi * 16 + l16) * AS_STR
                                     + kc * 16 + lhi));
#pragma unroll
            for (int p = 0; p < 4; p++) {
                uint32_t t4[4];
                ldmatrix_x4t(t4, smem_u32(Bb + (kc * 16 + l16) * BS_STR
                                          + wn * 64 + p * 16 + lhi));
                bu[slot][2 * p][0] = t4[0]; bu[slot][2 * p][1] = t4[1];
                bu[slot][2 * p + 1][0] = t4[2]; bu[slot][2 * p + 1][1] = t4[3];
            }
        };

        ldfrags(0, 0);
#pragma unroll
        for (int kc = 0; kc < 4; kc++) {
            const int cur = kc & 1;
            if (kc < 3) ldfrags(kc + 1, cur ^ 1);
#pragma unroll
            for (int mi = 0; mi < 2; mi++)
#pragma unroll
                for (int ni = 0; ni < 8; ni++)
                    mma_bf16(cf[mi][ni], au[cur][mi], bu[cur][ni]);
        }
    }

    // epilogue
#pragma unroll
    for (int mi = 0; mi < 2; mi++) {
        const int r = bm + wm * 32 + mi * 16 + g;
#pragma unroll
        for (int ni = 0; ni < 8; ni++) {
            const int c = bn + wn * 64 + ni * 8 + 2 * tig;
            float v0 = cf[mi][ni][0] + bias[c];
            float v1 = cf[mi][ni][1] + bias[c + 1];
            float v2 = cf[mi][ni][2] + bias[c];
            float v3 = cf[mi][ni][3] + bias[c + 1];
            if (QKV) {
                if ((c % 192) < 64) { v0 *= 0.125f; v1 *= 0.125f; v2 *= 0.125f; v3 *= 0.125f; }
                __nv_bfloat16* Cb = (__nv_bfloat16*)Cout;
                *(uint32_t*)(Cb + (size_t)r * N + c) = pack_bf16(v0, v1);
                *(uint32_t*)(Cb + (size_t)(r + 8) * N + c) = pack_bf16(v2, v3);
            } else {
                float* Cf = (float*)Cout;
                const float2 r0 = *(const float2*)(res + (size_t)r * N + c);
                const float2 r1 = *(const float2*)(res + (size_t)(r + 8) * N + c);
                *(float2*)(Cf + (size_t)r * N + c) = make_float2(v0 + r0.x, v1 + r0.y);
                *(float2*)(Cf + (size_t)(r + 8) * N + c) = make_float2(v2 + r1.x, v3 + r1.y);
            }
        }
    }
}

// ============================================================================
// Flash attention, bf16 MMA, register-resident softmax, 4-stage KV ring
// (prefetch issued right after the barrier), fragment double-buffering for
// K-frags (under S MMAs) and V-frags (kc=0 prefetched under softmax math).
// ============================================================================
#define TS 72
#define ATTN_Q_ELE (128 * TS)
#define ATTN_KV_ELE (64 * TS)
#define ATTN_STAGE_ELE (2 * ATTN_KV_ELE)
#define ATTN_SMEM_BYTES ((ATTN_Q_ELE + 4 * ATTN_STAGE_ELE) * 2)  // 92160

__global__ __launch_bounds__(256)
void attn_bf16_kernel(const __nv_bfloat16* __restrict__ qkv,
                      __nv_bfloat16* __restrict__ ctx)
{
    extern __shared__ __align__(16) __nv_bfloat16 sha[];
    __nv_bfloat16* Qs = sha;
    __nv_bfloat16* KV = sha + ATTN_Q_ELE;

    const int bh = blockIdx.x, qt = blockIdx.y;
    const int b = bh >> 4, h = bh & 15;
    const __nv_bfloat16* base = qkv + (size_t)b * SS * NQKV + h * (3 * HDIM);

    const int tid = threadIdx.x;
    const int w = tid >> 5, lane = tid & 31;
    const int g = lane >> 2, tig = lane & 3;
    const int l16 = lane & 15;
    const int lhi = (lane >> 4) * 8;

    auto load_kv = [&](int kt, int st) {
        __nv_bfloat16* Ks = KV + st * ATTN_STAGE_ELE;
        __nv_bfloat16* Vs = Ks + ATTN_KV_ELE;
#pragma unroll
        for (int i = 0; i < 2; i++) {
            int l = tid + i * 256;
            int row = l >> 3, seg = l & 7;
            const __nv_bfloat16* gp = base + (size_t)(kt * 64 + row) * NQKV + seg * 8;
            cpasync16(smem_u32(Ks + row * TS + seg * 8), gp + HDIM);
            cpasync16(smem_u32(Vs + row * TS + seg * 8), gp + 2 * HDIM);
        }
    };

#pragma unroll
    for (int i = 0; i < 4; i++) {
        int l = tid + i * 256;
        int row = l >> 3, seg = l & 7;
        cpasync16(smem_u32(Qs + row * TS + seg * 8),
                  base + (size_t)(qt * 128 + row) * NQKV + seg * 8);
    }
    load_kv(0, 0); CP_COMMIT();
    load_kv(1, 1); CP_COMMIT();
    load_kv(2, 2); CP_COMMIT();

    uint32_t qf[4][4];
    float o[8][4];
#pragma unroll
    for (int ni = 0; ni < 8; ni++)
#pragma unroll
        for (int q = 0; q < 4; q++) o[ni][q] = 0.0f;
    float m_lo = -1e30f, m_hi = -1e30f, l_lo = 0.0f, l_hi = 0.0f;

    for (int kt = 0; kt < 32; kt++) {
        if (kt <= 29)      { CP_WAIT2(); }
        else if (kt == 30) { CP_WAIT1(); }
        else               { CP_WAIT0(); }
        __syncthreads();

        // prefetch next KV stage now — slot (kt+3)&3 != kt&3, safe
        if (kt + 3 < 32) { load_kv(kt + 3, (kt + 3) & 3); CP_COMMIT(); }

        if (kt == 0) {
#pragma unroll
            for (int kc = 0; kc < 4; kc++)
                ldmatrix_x4(qf[kc], smem_u32(Qs + (w * 16 + l16) * TS + kc * 16 + lhi));
        }

        const __nv_bfloat16* Kb = KV + (kt & 3) * ATTN_STAGE_ELE;
        const __nv_bfloat16* Vb = Kb + ATTN_KV_ELE;

        // ---- S = Q K^T (K-frags double-buffered) ----
        uint32_t kf[2][4][4];
        auto ldK = [&](int kc, int slot) {
#pragma unroll
            for (int p = 0; p < 4; p++)
                ldmatrix_x4(kf[slot][p],
                            smem_u32(Kb + (p * 16 + ((lane >> 4) << 3) + (lane & 7)) * TS
                                     + kc * 16 + (((lane >> 3) & 1) << 3)));
        };

        float sfr[8][4];
#pragma unroll
        for (int ni = 0; ni < 8; ni++)
#pragma unroll
            for (int q = 0; q < 4; q++) sfr[ni][q] = 0.0f;

        ldK(0, 0);
#pragma unroll
        for (int kc = 0; kc < 4; kc++) {
            const int cur = kc & 1;
            if (kc < 3) ldK(kc + 1, cur ^ 1);
#pragma unroll
            for (int p = 0; p < 4; p++) {
                mma_bf16(sfr[2 * p],     qf[kc], &kf[cur][p][0]);
                mma_bf16(sfr[2 * p + 1], qf[kc], &kf[cur][p][2]);
            }
        }

        // prefetch V kc=0 frags — LDSM latency hides under softmax math
        uint32_t vf[2][4][4];
        auto ldV = [&](int kc, int slot) {
#pragma unroll
            for (int p = 0; p < 4; p++)
                ldmatrix_x4t(vf[slot][p],
                             smem_u32(Vb + (kc * 16 + l16) * TS + p * 16 + lhi));
        };
        ldV(0, 0);

        // ---- online softmax (register-resident, quad shuffles) ----
        float tl = -1e30f, th = -1e30f;
#pragma unroll
        for (int ni = 0; ni < 8; ni++) {
            tl = fmaxf(tl, fmaxf(sfr[ni][0], sfr[ni][1]));
            th = fmaxf(th, fmaxf(sfr[ni][2], sfr[ni][3]));
        }
        tl = fmaxf(tl, __shfl_xor_sync(0xffffffffu, tl, 1));
        tl = fmaxf(tl, __shfl_xor_sync(0xffffffffu, tl, 2));
        th = fmaxf(th, __shfl_xor_sync(0xffffffffu, th, 1));
        th = fmaxf(th, __shfl_xor_sync(0xffffffffu, th, 2));

        float mnl = fmaxf(m_lo, tl), mnh = fmaxf(m_hi, th);
        float al = __expf(m_lo - mnl), ah = __expf(m_hi - mnh);
        m_lo = mnl; m_hi = mnh;

        float sl = 0.0f, shi = 0.0f;
#pragma unroll
        for (int ni = 0; ni < 8; ni++) {
            sfr[ni][0] = __expf(sfr[ni][0] - m_lo);
            sfr[ni][1] = __expf(sfr[ni][1] - m_lo);
            sfr[ni][2] = __expf(sfr[ni][2] - m_hi);
            sfr[ni][3] = __expf(sfr[ni][3] - m_hi);
            sl  += sfr[ni][0] + sfr[ni][1];
            shi += sfr[ni][2] + sfr[ni][3];
        }
        l_lo = l_lo * al + sl;
        l_hi = l_hi * ah + shi;
#pragma unroll
        for (int ni = 0; ni < 8; ni++) {
            o[ni][0] *= al; o[ni][1] *= al;
            o[ni][2] *= ah; o[ni][3] *= ah;
        }

        uint32_t pu[4][4];
#pragma unroll
        for (int j = 0; j < 4; j++) {
            pu[j][0] = pack_bf16(sfr[2 * j][0],     sfr[2 * j][1]);
            pu[j][1] = pack_bf16(sfr[2 * j][2],     sfr[2 * j][3]);
            pu[j][2] = pack_bf16(sfr[2 * j + 1][0], sfr[2 * j + 1][1]);
            pu[j][3] = pack_bf16(sfr[2 * j + 1][2], sfr[2 * j + 1][3]);
        }

        // ---- O += P V (V-frags double-buffered) ----
#pragma unroll
        for (int kc = 0; kc < 4; kc++) {
            const int cur = kc & 1;
            if (kc < 3) ldV(kc + 1, cur ^ 1);
#pragma unroll
            for (int p = 0; p < 4; p++) {
                mma_bf16(o[2 * p],     pu[kc], &vf[cur][p][0]);
                mma_bf16(o[2 * p + 1], pu[kc], &vf[cur][p][2]);
            }
        }
    }

    l_lo += __shfl_xor_sync(0xffffffffu, l_lo, 1);
    l_lo += __shfl_xor_sync(0xffffffffu, l_lo, 2);
    l_hi += __shfl_xor_sync(0xffffffffu, l_hi, 1);
    l_hi += __shfl_xor_sync(0xffffffffu, l_hi, 2);
    const float il = 1.0f / l_lo, ih = 1.0f / l_hi;

    const int row0 = b * SS + qt * 128 + w * 16 + g;
#pragma unroll
    for (int ni = 0; ni < 8; ni++) {
        const int col = h * HDIM + ni * 8 + 2 * tig;
        *(uint32_t*)(ctx + (size_t)row0 * HH + col) =
            pack_bf16(o[ni][0] * il, o[ni][1] * il);
        *(uint32_t*)(ctx + (size_t)(row0 + 8) * HH + col) =
            pack_bf16(o[ni][2] * ih, o[ni][3] * ih);
    }
}

// ============================================================================
// LayerNorm over H=1024, one block per row.
// ============================================================================
__global__ __launch_bounds__(256)
void layernorm_kernel(const float* __restrict__ x, const float* __restrict__ gamma,
                      const float* __restrict__ beta, float* __restrict__ out)
{
    __shared__ float red[256];
    const int row = blockIdx.x;
    const int tid = threadIdx.x;

    const float4 v = ((const float4*)(x + (size_t)row * HH))[tid];
    float s = v.x + v.y + v.z + v.w;
    red[tid] = s;
    __syncthreads();
#pragma unroll
    for (int o = 128; o > 0; o >>= 1) {
        if (tid < o) red[tid] += red[tid + o];
        __syncthreads();
    }
    const float mu = red[0] * (1.0f / HH);
    __syncthreads();

    const float dx = v.x - mu, dy = v.y - mu, dz = v.z - mu, dw = v.w - mu;
    red[tid] = dx * dx + dy * dy + dz * dz + dw * dw;
    __syncthreads();
#pragma unroll
    for (int o = 128; o > 0; o >>= 1) {
        if (tid < o) red[tid] += red[tid + o];
        __syncthreads();
    }
    const float var = red[0] * (1.0f / HH);
    const float rstd = rsqrtf(var + 1e-5f);

    const float4 gm = ((const float4*)gamma)[tid];
    const float4 bt = ((const float4*)beta)[tid];
    float4 o;
    o.x = dx * rstd * gm.x + bt.x;
    o.y = dy * rstd * gm.y + bt.y;
    o.z = dz * rstd * gm.z + bt.z;
    o.w = dw * rstd * gm.w + bt.w;
    ((float4*)(out + (size_t)row * HH))[tid] = o;
}

// ============================================================================
extern "C" void kernel_launch(void* const* d_in, const int* in_sizes, int n_in,
                              void* d_out, int out_size)
{
    const float* hidden  = (const float*)d_in[0];
    const float* w_qkv   = (const float*)d_in[1];
    const float* b_qkv   = (const float*)d_in[2];
    const float* w_dense = (const float*)d_in[3];
    const float* b_dense = (const float*)d_in[4];
    const float* gamma   = (const float*)d_in[5];
    const float* beta    = (const float*)d_in[6];
    float* out = (float*)d_out;

    __nv_bfloat16 *hid, *wq, *wd, *qkv, *ctx;
    float* x;
    cudaGetSymbolAddress((void**)&hid, g_hid_bf);
    cudaGetSymbolAddress((void**)&wq,  g_wq_bf);
    cudaGetSymbolAddress((void**)&wd,  g_wd_bf);
    cudaGetSymbolAddress((void**)&qkv, g_qkv_bf);
    cudaGetSymbolAddress((void**)&ctx, g_ctx_bf);
    cudaGetSymbolAddress((void**)&x,   g_x);

    f2bf_kernel<<<(MTOT * HH) / 1024, 256>>>(hidden, hid);
    f2bf_kernel<<<(HH * NQKV) / 1024, 256>>>(w_qkv, wq);
    f2bf_kernel<<<(HH * HH) / 1024, 256>>>(w_dense, wd);

    cudaFuncSetAttribute(gemm_bf16_kernel<true>,
                         cudaFuncAttributeMaxDynamicSharedMemorySize, GEMM_SMEM_BYTES);
    gemm_bf16_kernel<true><<<dim3(NQKV / 128, MTOT / 128), 256, GEMM_SMEM_BYTES>>>(
        hid, wq, b_qkv, nullptr, qkv, HH, NQKV);

    cudaFuncSetAttribute(attn_bf16_kernel,
                         cudaFuncAttributeMaxDynamicSharedMemorySize, ATTN_SMEM_BYTES);
    attn_bf16_kernel<<<dim3(32, 16), 256, ATTN_SMEM_BYTES>>>(qkv, ctx);

    cudaFuncSetAttribute(gemm_bf16_kernel<false>,
                         cudaFuncAttributeMaxDynamicSharedMemorySize, GEMM_SMEM_BYTES);
    gemm_bf16_kernel<false><<<dim3(HH / 128, MTOT / 128), 256, GEMM_SMEM_BYTES>>>(
        ctx, wd, b_dense, hidden, x, HH, HH);

    layernorm_kernel<<<MTOT, 256>>>(x, gamma, beta, out);
}